// round 8
// baseline (speedup 1.0000x reference)
#include <cuda_runtime.h>
#include <cuda_fp16.h>
#include <cstdint>

#define BB 4
#define SS 2048
#define HH 8
#define DD 64
#define EE 512
#define BH (BB*HH)

// Scratch (allocation-free: __device__ globals)
__device__ __half g_Qh[BH*SS*DD];   // [b,h,s,d] fp16, pre-scaled by 0.125*log2(e)
__device__ __half g_Kt[BH*DD*SS];   // [b,h,d,s] fp16 (pre-transposed for MMA1 B)
__device__ __half g_Vh[BH*SS*DD];   // [b,h,s,d] fp16
__device__ __half g_AOh[BB*SS*EE];  // attention output fp16, pre-Wo
__device__ __half g_WoT[EE*EE];     // Wo transposed [k][e] fp16

// ============================ helpers ======================================
__device__ __forceinline__ uint32_t smem_u32(const void* p) {
    uint32_t a;
    asm("{ .reg .u64 t; cvta.to.shared.u64 t, %1; cvt.u32.u64 %0, t; }"
        : "=r"(a) : "l"(p));
    return a;
}
__device__ __forceinline__ uint32_t h2ex2(uint32_t x) {
    uint32_t r;
    asm("ex2.approx.f16x2 %0, %1;" : "=r"(r) : "r"(x));
    return r;
}
// fp16 inputs, fp32 accum
__device__ __forceinline__ void mma_f16(float* c, const uint32_t* a,
                                        uint32_t b0, uint32_t b1) {
    asm volatile("mma.sync.aligned.m16n8k16.row.col.f32.f16.f16.f32 "
        "{%0,%1,%2,%3}, {%4,%5,%6,%7}, {%8,%9}, {%0,%1,%2,%3};"
        : "+f"(c[0]), "+f"(c[1]), "+f"(c[2]), "+f"(c[3])
        : "r"(a[0]), "r"(a[1]), "r"(a[2]), "r"(a[3]), "r"(b0), "r"(b1));
}
// fp16 inputs, fp16 accum (C/D = 2 x b32 packed half2)
__device__ __forceinline__ void mma_f16f16(uint32_t* c, const uint32_t* a,
                                           uint32_t b0, uint32_t b1) {
    asm volatile("mma.sync.aligned.m16n8k16.row.col.f16.f16.f16.f16 "
        "{%0,%1}, {%2,%3,%4,%5}, {%6,%7}, {%0,%1};"
        : "+r"(c[0]), "+r"(c[1])
        : "r"(a[0]), "r"(a[1]), "r"(a[2]), "r"(a[3]), "r"(b0), "r"(b1));
}
__device__ __forceinline__ void ldmx4(uint32_t* r, uint32_t addr) {
    asm volatile("ldmatrix.sync.aligned.m8n8.x4.shared.b16 {%0,%1,%2,%3}, [%4];"
        : "=r"(r[0]), "=r"(r[1]), "=r"(r[2]), "=r"(r[3]) : "r"(addr));
}
__device__ __forceinline__ void ldmx4t(uint32_t* r, uint32_t addr) {
    asm volatile("ldmatrix.sync.aligned.m8n8.x4.trans.shared.b16 {%0,%1,%2,%3}, [%4];"
        : "=r"(r[0]), "=r"(r[1]), "=r"(r[2]), "=r"(r[3]) : "r"(addr));
}
__device__ __forceinline__ void ldmx2t(uint32_t* r, uint32_t addr) {
    asm volatile("ldmatrix.sync.aligned.m8n8.x2.trans.shared.b16 {%0,%1}, [%2];"
        : "=r"(r[0]), "=r"(r[1]) : "r"(addr));
}
__device__ __forceinline__ void cp16(uint32_t dst, const void* src) {
    asm volatile("cp.async.cg.shared.global [%0], [%1], 16;"
                 :: "r"(dst), "l"(src));
}
#define CP_COMMIT() asm volatile("cp.async.commit_group;" ::: "memory")
#define CP_WAIT0()  asm volatile("cp.async.wait_group 0;" ::: "memory")
#define CP_WAIT1()  asm volatile("cp.async.wait_group 1;" ::: "memory")

// ---------------------------------------------------------------------------
// Kernel 0: Wo -> WoT[k][e] fp16 (tiny, one-time transpose+convert)
// ---------------------------------------------------------------------------
__global__ void wo_prep_kernel(const float* __restrict__ Wo)
{
    __shared__ float t[32][33];
    const int bx = blockIdx.x * 32, by = blockIdx.y * 32;
    const int tx = threadIdx.x, ty = threadIdx.y;
    #pragma unroll
    for (int j = 0; j < 4; j++)
        t[ty + 8*j][tx] = Wo[(by + ty + 8*j)*EE + bx + tx];
    __syncthreads();
    #pragma unroll
    for (int j = 0; j < 4; j++)
        g_WoT[(bx + ty + 8*j)*EE + by + tx] = __float2half(t[tx][ty + 8*j]);
}

// ---------------------------------------------------------------------------
// Kernel 1: QKV projection via fp16 mma.sync (all from queries, per ref bug).
// All three weight tiles preloaded once; one barrier pair for the whole CTA.
// Q is pre-scaled by 0.125*log2(e) so attention softmax is a bare ex2.
// ---------------------------------------------------------------------------
__global__ __launch_bounds__(256, 2) void proj_kernel(
    const float* __restrict__ X,
    const float* __restrict__ Wq,
    const float* __restrict__ Wk,
    const float* __restrict__ Wv)
{
    __shared__ __half Xh[128*72];       // 18432 B
    __shared__ __half Wh[3*64*72];      // 27648 B
    const uint32_t xbase = smem_u32(Xh);

    const int bh = blockIdx.y;
    const int b  = bh >> 3, h = bh & 7;
    const int s0 = blockIdx.x * 128;
    const int tid = threadIdx.x;
    const int wid = tid >> 5, lane = tid & 31;
    const int wq = wid >> 1, we = wid & 1;
    const int R0 = wq * 32, E0 = we * 32;
    const int qr = lane >> 2, qc = lane & 3;

    #pragma unroll
    for (int i = 0; i < 8; i++) {
        int f = tid + 256*i;
        int r = f >> 4, c4 = (f & 15) << 2;
        float4 v = *(const float4*)&X[((size_t)b*SS + s0 + r)*EE + h*DD + c4];
        *(__half2*)&Xh[r*72 + c4]     = __floats2half2_rn(v.x, v.y);
        *(__half2*)&Xh[r*72 + c4 + 2] = __floats2half2_rn(v.z, v.w);
    }
    #pragma unroll
    for (int w = 0; w < 3; w++) {
        const float* W = (w == 0) ? Wq : (w == 1) ? Wk : Wv;
        #pragma unroll
        for (int i = 0; i < 4; i++) {
            int f = tid + 256*i;
            int e = f >> 4, c4 = (f & 15) << 2;
            float4 v = *(const float4*)&W[e*64 + c4];
            *(__half2*)&Wh[w*64*72 + e*72 + c4]     = __floats2half2_rn(v.x, v.y);
            *(__half2*)&Wh[w*64*72 + e*72 + c4 + 2] = __floats2half2_rn(v.z, v.w);
        }
    }
    __syncthreads();

    #pragma unroll
    for (int w = 0; w < 3; w++) {
        const __half* Wb = &Wh[w*64*72];

        float c[2][4][4];
        #pragma unroll
        for (int m = 0; m < 2; m++)
            #pragma unroll
            for (int n = 0; n < 4; n++)
                #pragma unroll
                for (int r = 0; r < 4; r++) c[m][n][r] = 0.f;

        #pragma unroll
        for (int t = 0; t < 4; t++) {
            uint32_t qa[2][4];
            #pragma unroll
            for (int m = 0; m < 2; m++)
                ldmx4(qa[m], xbase +
                    ((uint32_t)(R0 + 16*m + (lane & 15))*72 + t*16 + (lane >> 4)*8)*2);
            #pragma unroll
            for (int n = 0; n < 4; n++) {
                int jj = E0 + n*8 + qr;
                uint32_t b0 = *(const uint32_t*)&Wb[jj*72 + t*16 + qc*2];
                uint32_t b1 = *(const uint32_t*)&Wb[jj*72 + t*16 + qc*2 + 8];
                mma_f16(c[0][n], qa[0], b0, b1);
                mma_f16(c[1][n], qa[1], b0, b1);
            }
        }

        if (w == 1) {
            #pragma unroll
            for (int m = 0; m < 2; m++)
                #pragma unroll
                for (int n = 0; n < 4; n++) {
                    int e = E0 + n*8 + qc*2;
                    int s = s0 + R0 + 16*m + qr;
                    g_Kt[((size_t)bh*DD + e  )*SS + s]   = __float2half(c[m][n][0]);
                    g_Kt[((size_t)bh*DD + e+1)*SS + s]   = __float2half(c[m][n][1]);
                    g_Kt[((size_t)bh*DD + e  )*SS + s+8] = __float2half(c[m][n][2]);
                    g_Kt[((size_t)bh*DD + e+1)*SS + s+8] = __float2half(c[m][n][3]);
                }
        } else {
            const float scl = (w == 0) ? 0.18033688011112042f : 1.0f;
            __half* dst = (w == 0) ? g_Qh : g_Vh;
            #pragma unroll
            for (int m = 0; m < 2; m++)
                #pragma unroll
                for (int n = 0; n < 4; n++) {
                    int e = E0 + n*8 + qc*2;
                    int s = s0 + R0 + 16*m + qr;
                    *(__half2*)&dst[((size_t)bh*SS + s)*DD + e] =
                        __floats2half2_rn(c[m][n][0]*scl, c[m][n][1]*scl);
                    *(__half2*)&dst[((size_t)bh*SS + s+8)*DD + e] =
                        __floats2half2_rn(c[m][n][2]*scl, c[m][n][3]*scl);
                }
        }
    }
}

// ---------------------------------------------------------------------------
// Attention stage loader: cp.async K (transposed [64][136]) + V ([128][72]).
// (Ones-columns of V, cols 64-71, are constant; written once per buffer.)
// ---------------------------------------------------------------------------
__device__ __forceinline__ void load_kv_stage(
    uint32_t kaddr, uint32_t vaddr, int bh, int kt, int tid)
{
    #pragma unroll
    for (int i = 0; i < 4; i++) {
        int f = tid + 256*i;
        int d = f >> 4, c8 = (f & 15) << 3;
        cp16(kaddr + (uint32_t)(d*136 + c8)*2,
             &g_Kt[((size_t)bh*DD + d)*SS + (size_t)kt*128 + c8]);
        int r = f >> 3, v8 = (f & 7) << 3;
        cp16(vaddr + (uint32_t)(r*72 + v8)*2,
             &g_Vh[((size_t)bh*SS + (size_t)kt*128 + r)*DD + v8]);
    }
}

// ---------------------------------------------------------------------------
// Kernel 2: FA2-style attention, all-fp16-accum mma, 3-stage cp.async, 2 CTA/SM.
// CTA: 128 q-rows, 256 thr / 8 warps. Warp = 16 q-rows x full 128 j.
// Q fragments in registers. MMA1 f16-acc; its C-frags are MMA2 A-frags after
// ex2.f16x2. MMA2 + lsum column ALSO f16-acc, flushed to fp32 shadows per kt.
// Smem: 3 x (Kt[64][136] + Vh[128][72]) = 105 KB.
// ---------------------------------------------------------------------------
__global__ __launch_bounds__(256, 2) void attn_kernel()
{
    extern __shared__ char smb[];
    const int STG = 17408 + 18432;            // 35840 B per stage

    const int bh = blockIdx.y;
    const int b  = bh >> 3, h = bh & 7;
    const int q0 = blockIdx.x * 128;
    const int tid = threadIdx.x;
    const int wid = tid >> 5, lane = tid & 31;
    const int qr = lane >> 2, qc = lane & 3;
    const int W0 = wid * 16;                  // warp's q-row base
    const uint32_t sbase = smem_u32(smb);
    uint32_t kb[3], vb[3];
    #pragma unroll
    for (int i = 0; i < 3; i++) {
        kb[i] = sbase + i*STG;
        vb[i] = kb[i] + 17408;
    }

    // ---- stage Q through buffer-0 V region, load A-frags to registers ----
    #pragma unroll
    for (int i = 0; i < 4; i++) {
        int f = tid + 256*i;
        int r = f >> 3, c8 = (f & 7) << 3;
        cp16(vb[0] + (uint32_t)(r*72 + c8)*2,
             &g_Qh[((size_t)bh*SS + q0 + r)*DD + c8]);
    }
    CP_COMMIT(); CP_WAIT0();
    __syncthreads();
    uint32_t qa[4][4];
    #pragma unroll
    for (int t = 0; t < 4; t++)
        ldmx4(qa[t], vb[0] +
            ((uint32_t)(W0 + (lane & 15))*72 + t*16 + (lane >> 4)*8)*2);
    __syncthreads();    // all Q reads done before pipeline overwrites vb[0]

    // ones-columns (V cols 64-71) for all three buffers
    if (tid < 128) {
        const uint4 ones = make_uint4(0x00003C00u, 0u, 0u, 0u);
        #pragma unroll
        for (int i = 0; i < 3; i++)
            *(uint4*)(smb + (i*STG + 17408) + (tid*72 + 64)*2) = ones;
    }

    load_kv_stage(kb[0], vb[0], bh, 0, tid); CP_COMMIT();
    load_kv_stage(kb[1], vb[1], bh, 1, tid); CP_COMMIT();

    float o[8][4];
    float oL0 = 0.f, oL1 = 0.f;
    #pragma unroll
    for (int n = 0; n < 8; n++)
        #pragma unroll
        for (int r = 0; r < 4; r++) o[n][r] = 0.f;

    for (int kt = 0; kt < SS/128; kt++) {
        const int cur = kt % 3;
        CP_WAIT1();
        __syncthreads();
        if (kt + 2 < SS/128) {
            const int nxt = (kt + 2) % 3;
            load_kv_stage(kb[nxt], vb[nxt], bh, kt+2, tid);
            CP_COMMIT();
        }

        // f16 accumulators for this kt (flushed to fp32 after the jc loop)
        uint32_t o16[8][2], oL16[2];
        #pragma unroll
        for (int n = 0; n < 8; n++) { o16[n][0] = 0u; o16[n][1] = 0u; }
        oL16[0] = 0u; oL16[1] = 0u;

        #pragma unroll
        for (int jc = 0; jc < 8; jc++) {
            // ---- MMA1: S(16q x 16j) over k=64, fp16 accumulators ----
            uint32_t sA[2] = {0u, 0u}, sB[2] = {0u, 0u};
            #pragma unroll
            for (int t = 0; t < 4; t++) {
                uint32_t kr[4];
                ldmx4t(kr, kb[cur] +
                    ((uint32_t)(t*16 + (lane & 15))*136 + jc*16 + (lane >> 4)*8)*2);
                mma_f16f16(sA, qa[t], kr[0], kr[1]);
                mma_f16f16(sB, qa[t], kr[2], kr[3]);
            }
            // ---- P = ex2(S): C-frags become MMA2 A-frags directly ----
            uint32_t pa[4];
            pa[0] = h2ex2(sA[0]);
            pa[1] = h2ex2(sA[1]);
            pa[2] = h2ex2(sB[0]);
            pa[3] = h2ex2(sB[1]);

            // ---- MMA2 (f16 acc): O16 += P_chunk V_chunk; lsum via ones ----
            #pragma unroll
            for (int db = 0; db < 4; db++) {
                uint32_t vr[4];
                ldmx4t(vr, vb[cur] +
                    ((uint32_t)(jc*16 + (lane & 15))*72 + db*16 + (lane >> 4)*8)*2);
                mma_f16f16(o16[db*2],   pa, vr[0], vr[1]);
                mma_f16f16(o16[db*2+1], pa, vr[2], vr[3]);
            }
            uint32_t er[2];
            ldmx2t(er, vb[cur] +
                ((uint32_t)(jc*16 + (lane & 15))*72 + 64)*2);
            mma_f16f16(oL16, pa, er[0], er[1]);
        }

        // ---- flush f16 partials into fp32 shadows (idle fma pipe) ----
        #pragma unroll
        for (int n = 0; n < 8; n++) {
            float2 lo = __half22float2(*(__half2*)&o16[n][0]);
            float2 hi = __half22float2(*(__half2*)&o16[n][1]);
            o[n][0] += lo.x; o[n][1] += lo.y;
            o[n][2] += hi.x; o[n][3] += hi.y;
        }
        oL0 += __low2float(*(__half2*)&oL16[0]);
        oL1 += __low2float(*(__half2*)&oL16[1]);
    }

    // ---- epilogue: lsum broadcast within quad, normalize, store fp16 ----
    float ls0 = __shfl_sync(0xffffffffu, oL0, lane & ~3);
    float ls1 = __shfl_sync(0xffffffffu, oL1, lane & ~3);
    const float inv0 = 1.f / ls0;
    const float inv1 = 1.f / ls1;
    const int row0 = q0 + W0 + qr;
    __half* d0 = &g_AOh[((size_t)b*SS + row0)*EE + h*DD];
    __half* d1 = d0 + (size_t)8*EE;
    #pragma unroll
    for (int n = 0; n < 8; n++) {
        *(__half2*)&d0[n*8 + 2*qc] = __floats2half2_rn(o[n][0]*inv0, o[n][1]*inv0);
        *(__half2*)&d1[n*8 + 2*qc] = __floats2half2_rn(o[n][2]*inv1, o[n][3]*inv1);
    }
}

// ---------------------------------------------------------------------------
// Kernel 3: out = AO @ Wo^T + bo, fp16 mma, 3-stage cp.async, 2 CTA/SM.
// Smem: 3 x (As[128][72] + Ws[64][136]) = 105 KB.
// ---------------------------------------------------------------------------
__global__ __launch_bounds__(256, 2) void outproj_kernel(
    const float* __restrict__ bo, float* __restrict__ out)
{
    extern __shared__ char osmb[];
    const int STG = 18432 + 17408;
    const uint32_t sbase = smem_u32(osmb);
    uint32_t ab[3], wb[3];
    #pragma unroll
    for (int i = 0; i < 3; i++) {
        ab[i] = sbase + i*STG;
        wb[i] = ab[i] + 18432;
    }

    const int r0 = blockIdx.y * 128;
    const int e0 = blockIdx.x * 128;
    const int tid = threadIdx.x;
    const int wid = tid >> 5, lane = tid & 31;
    const int wq = wid >> 1, we = wid & 1;
    const int R0 = wq * 32, E0 = we * 64;
    const int qr = lane >> 2, qc = lane & 3;

    float c[2][8][4];
    #pragma unroll
    for (int m = 0; m < 2; m++)
        #pragma unroll
        for (int n = 0; n < 8; n++)
            #pragma unroll
            for (int r = 0; r < 4; r++) c[m][n][r] = 0.f;

    auto issue = [&](int st, int kc) {
        #pragma unroll
        for (int i = 0; i < 4; i++) {
            int f = tid + 256*i;
            int r = f >> 3, c8 = (f & 7) << 3;
            cp16(ab[st] + (uint32_t)(r*72 + c8)*2,
                 &g_AOh[(size_t)(r0 + r)*EE + kc*64 + c8]);
            int d = f >> 4, w8 = (f & 15) << 3;
            cp16(wb[st] + (uint32_t)(d*136 + w8)*2,
                 &g_WoT[(size_t)(kc*64 + d)*EE + e0 + w8]);
        }
        CP_COMMIT();
    };

    issue(0, 0);
    issue(1, 1);

    for (int kc = 0; kc < 8; kc++) {
        const int cur = kc % 3;
        CP_WAIT1();
        __syncthreads();
        if (kc + 2 < 8) issue((kc + 2) % 3, kc + 2);

        #pragma unroll
        for (int t = 0; t < 4; t++) {
            uint32_t qa[2][4];
            #pragma unroll
            for (int m = 0; m < 2; m++)
                ldmx4(qa[m], ab[cur] +
                    ((uint32_t)(R0 + 16*m + (lane & 15))*72 + t*16 + (lane >> 4)*8)*2);
            #pragma unroll
            for (int db = 0; db < 4; db++) {
                uint32_t wr[4];
                ldmx4t(wr, wb[cur] +
                    ((uint32_t)(t*16 + (lane & 15))*136 + E0 + db*16 + (lane >> 4)*8)*2);
                mma_f16(c[0][db*2],   qa[0], wr[0], wr[1]);
                mma_f16(c[1][db*2],   qa[1], wr[0], wr[1]);
                mma_f16(c[0][db*2+1], qa[0], wr[2], wr[3]);
                mma_f16(c[1][db*2+1], qa[1], wr[2], wr[3]);
            }
        }
    }

    #pragma unroll
    for (int m = 0; m < 2; m++)
        #pragma unroll
        for (int n = 0; n < 8; n++) {
            int e = e0 + E0 + n*8 + qc*2;
            float b0 = bo[e], b1 = bo[e+1];
            int r = r0 + R0 + 16*m + qr;
            *(float2*)&out[(size_t)r*EE + e] =
                make_float2(c[m][n][0] + b0, c[m][n][1] + b1);
            *(float2*)&out[(size_t)(r+8)*EE + e] =
                make_float2(c[m][n][2] + b0, c[m][n][3] + b1);
        }
}

// ---------------------------------------------------------------------------
extern "C" void kernel_launch(void* const* d_in, const int* in_sizes, int n_in,
                              void* d_out, int out_size)
{
    const float* queries = (const float*)d_in[0];
    // d_in[1]/d_in[2] unused: reference derives K and V from queries.
    const float* Wq = (const float*)d_in[3];
    const float* Wk = (const float*)d_in[4];
    const float* Wv = (const float*)d_in[5];
    const float* Wo = (const float*)d_in[6];
    const float* bo = (const float*)d_in[7];
    float* out = (float*)d_out;

    const int ATTN_SMEM = 3 * (17408 + 18432);   // 107520 B
    const int OP_SMEM   = 3 * (18432 + 17408);   // 107520 B
    cudaFuncSetAttribute(attn_kernel,
        cudaFuncAttributeMaxDynamicSharedMemorySize, ATTN_SMEM);
    cudaFuncSetAttribute(outproj_kernel,
        cudaFuncAttributeMaxDynamicSharedMemorySize, OP_SMEM);

    wo_prep_kernel<<<dim3(16,16), dim3(32,8)>>>(Wo);
    proj_kernel<<<dim3(SS/128, BH), 256>>>(queries, Wq, Wk, Wv);
    attn_kernel<<<dim3(SS/128, BH), 256, ATTN_SMEM>>>();
    outproj_kernel<<<dim3(EE/128, (BB*SS)/128), 256, OP_SMEM>>>(bo, out);
}